// round 15
// baseline (speedup 1.0000x reference)
#include <cuda_runtime.h>
#include <cuda_fp16.h>
#include <math.h>
#include <stdint.h>

#define S_TOK 8192
#define DIM   1024
#define FDIM  4096
#define NE    8
#define CAP   2560
#define NA    (S_TOK * 2)
#define NBLK_ROUTE (S_TOK / 8)

// ---------------- static scratch ----------------
__device__ __align__(256) float g_impb[NBLK_ROUTE * NE];
__device__ __align__(256) int   g_topk_e[NA];
__device__ __align__(256) float g_topk_g[NA];
__device__ __align__(256) int   g_pos[NA];
__device__ __align__(256) int   g_rowsrc[NE * CAP];
__device__ __align__(256) float g_gatew[NE * CAP];
__device__ __align__(256) int   g_rows_used[NE];
__device__ __align__(256) __half g_xbuf[(size_t)NE * CAP * DIM];
__device__ __align__(256) __half g_h[(size_t)NE * CAP * FDIM];
__device__ __align__(256) __half g_w1h[(size_t)NE * FDIM * DIM];
__device__ __align__(256) __half g_w2h[(size_t)NE * DIM * FDIM];

// ---------------- helpers ----------------
__device__ __forceinline__ uint32_t smem_u32(const void* p) {
    uint32_t r;
    asm("{ .reg .u64 t; cvta.to.shared.u64 t, %1; cvt.u32.u64 %0, t; }" : "=r"(r) : "l"(p));
    return r;
}
__device__ __forceinline__ void cpa16(uint32_t s, const void* g) {
    asm volatile("cp.async.cg.shared.global [%0], [%1], 16;" :: "r"(s), "l"(g));
}
#define CP_COMMIT() asm volatile("cp.async.commit_group;")

__device__ __forceinline__ void ldsm4(uint32_t addr, uint32_t& r0, uint32_t& r1,
                                      uint32_t& r2, uint32_t& r3) {
    asm volatile("ldmatrix.sync.aligned.m8n8.x4.shared.b16 {%0,%1,%2,%3}, [%4];"
                 : "=r"(r0), "=r"(r1), "=r"(r2), "=r"(r3) : "r"(addr));
}
__device__ __forceinline__ void mma_f16(float& c0, float& c1, float& c2, float& c3,
                                        uint32_t a0, uint32_t a1, uint32_t a2, uint32_t a3,
                                        uint32_t b0, uint32_t b1) {
    asm volatile("mma.sync.aligned.m16n8k16.row.col.f32.f16.f16.f32 "
                 "{%0,%1,%2,%3}, {%4,%5,%6,%7}, {%8,%9}, {%0,%1,%2,%3};"
                 : "+f"(c0), "+f"(c1), "+f"(c2), "+f"(c3)
                 : "r"(a0), "r"(a1), "r"(a2), "r"(a3), "r"(b0), "r"(b1));
}

// ---------------- route + weight conversion + y-zero, one kernel ----------------
#define NCONV 4096
#define W1F4 ((size_t)NE * FDIM * DIM / 4)     // 8388608 float4 per weight

__global__ void k_route_conv(const float* __restrict__ x, const float* __restrict__ wg,
                             const float* __restrict__ W1, const float* __restrict__ W2,
                             float* __restrict__ out) {
    int bid = blockIdx.x;
    int tid = threadIdx.x;

    if (bid >= NBLK_ROUTE) {
        // ---- weight fp16 conversion: 4096 blocks x 16 float4/thread ----
        size_t base4 = (size_t)(bid - NBLK_ROUTE) * 4096 + tid;
#pragma unroll
        for (int k = 0; k < 16; k++) {
            size_t i4 = base4 + (size_t)k * 256;
            const float4* src;
            __half* dst;
            size_t off;
            if (i4 < W1F4) { src = (const float4*)W1; dst = g_w1h; off = i4; }
            else           { src = (const float4*)W2; dst = g_w2h; off = i4 - W1F4; }
            float4 v = src[off];
            __half h[4] = { __float2half_rn(v.x), __float2half_rn(v.y),
                            __float2half_rn(v.z), __float2half_rn(v.w) };
            *(uint2*)(dst + off * 4) = *(uint2*)h;
        }
        return;
    }

    // ---- zero this block's slice of y (2048 float4 per block) ----
    {
        float4* o4 = (float4*)out + (size_t)bid * 2048 + tid;
        float4 z = make_float4(0.f, 0.f, 0.f, 0.f);
#pragma unroll
        for (int k = 0; k < 8; k++) o4[k * 256] = z;
    }

    // ---- routing: warp per token ----
    __shared__ float sw[NE * DIM];
    __shared__ float simp[NE];

    const float4* wg4 = (const float4*)wg;
    float4* sw4 = (float4*)sw;
    for (int i = tid; i < NE * DIM / 4; i += 256) sw4[i] = wg4[i];
    if (tid < NE) simp[tid] = 0.f;
    __syncthreads();

    int warp = tid >> 5, lane = tid & 31;
    int t = bid * 8 + warp;

    const float4* x4 = (const float4*)(x + (size_t)t * DIM);
    float acc[NE];
#pragma unroll
    for (int e = 0; e < NE; e++) acc[e] = 0.f;
#pragma unroll
    for (int i = 0; i < 8; i++) {
        float4 xv = x4[lane + i * 32];
#pragma unroll
        for (int e = 0; e < NE; e++) {
            float4 wv = ((const float4*)(sw + e * DIM))[lane + i * 32];
            acc[e] += xv.x * wv.x + xv.y * wv.y + xv.z * wv.z + xv.w * wv.w;
        }
    }
#pragma unroll
    for (int e = 0; e < NE; e++) {
#pragma unroll
        for (int off = 16; off > 0; off >>= 1)
            acc[e] += __shfl_xor_sync(0xffffffffu, acc[e], off);
    }

    if (lane == 0) {
        float m = acc[0];
#pragma unroll
        for (int e = 1; e < NE; e++) m = fmaxf(m, acc[e]);
        float p[NE];
        float s = 0.f;
#pragma unroll
        for (int e = 0; e < NE; e++) { p[e] = expf(acc[e] - m); s += p[e]; }
        float inv = 1.f / s;
#pragma unroll
        for (int e = 0; e < NE; e++) { p[e] *= inv; atomicAdd(&simp[e], p[e]); }

        int e0 = 0;
#pragma unroll
        for (int e = 1; e < NE; e++) if (p[e] > p[e0]) e0 = e;
        int e1 = (e0 == 0) ? 1 : 0;
#pragma unroll
        for (int e = 0; e < NE; e++) if (e != e0 && p[e] > p[e1]) e1 = e;

        g_topk_e[2 * t]     = e0;  g_topk_g[2 * t]     = p[e0];
        g_topk_e[2 * t + 1] = e1;  g_topk_g[2 * t + 1] = p[e1];
    }
    __syncthreads();
    if (tid < NE) g_impb[bid * NE + tid] = simp[tid];
}

// ---------------- exact arrival-order capacity scan + aux loss ----------------
__global__ void k_scan(float* __restrict__ out, int out_size) {
    __shared__ int scnt[256][NE];
    __shared__ int stot[NE];
    __shared__ float simp[NE];
    int tid = threadIdx.x;

    if (tid < NE) simp[tid] = 0.f;
    __syncthreads();
    {
        float part = 0.f;
        int e = tid & 7;
        for (int i = tid >> 3; i < NBLK_ROUTE; i += 32) part += g_impb[i * NE + e];
        atomicAdd(&simp[e], part);
    }

    int cnt[NE];
#pragma unroll
    for (int e = 0; e < NE; e++) cnt[e] = 0;
    int base = tid * 64;
    for (int j = 0; j < 64; j++) cnt[g_topk_e[base + j]]++;
#pragma unroll
    for (int e = 0; e < NE; e++) scnt[tid][e] = cnt[e];
    __syncthreads();

    if (tid < NE) {
        int run = 0;
        for (int i = 0; i < 256; i++) {
            int v = scnt[i][tid];
            scnt[i][tid] = run;
            run += v;
        }
        stot[tid] = run;
        g_rows_used[tid] = run < CAP ? run : CAP;
    }
    __syncthreads();

#pragma unroll
    for (int e = 0; e < NE; e++) cnt[e] = scnt[tid][e];
    for (int j = 0; j < 64; j++) {
        int a = base + j;
        int e = g_topk_e[a];
        int p = cnt[e]++;
        g_pos[a] = p;
        if (p < CAP) {
            g_rowsrc[e * CAP + p] = a >> 1;
            g_gatew[e * CAP + p] = g_topk_g[a];
        }
    }

    if (tid == 0) {
        float ssum = 0.f;
        for (int e = 0; e < NE; e++)
            ssum += (simp[e] / (float)S_TOK) * ((float)stot[e] / (float)S_TOK);
        if (out_size > S_TOK * DIM) out[S_TOK * DIM] = (float)NE * ssum;
    }
}

// ---------------- dispatch tokens (fp16) ----------------
__global__ void k_dispatch(const float* __restrict__ x) {
    int p = blockIdx.x, e = blockIdx.y;
    int tid = threadIdx.x;
    size_t base = ((size_t)e * CAP + p) * DIM + tid * 4;
    float4 v;
    if (p < g_rows_used[e]) {
        v = *(const float4*)(x + (size_t)g_rowsrc[e * CAP + p] * DIM + tid * 4);
    } else {
        v = make_float4(0.f, 0.f, 0.f, 0.f);
    }
    __half h[4] = { __float2half_rn(v.x), __float2half_rn(v.y),
                    __float2half_rn(v.z), __float2half_rn(v.w) };
    *(uint2*)(g_xbuf + base) = *(uint2*)h;
}

// ---------------- mma.sync fp16 FFN GEMM: 128x128 tile, 8 warps, 2 CTAs/SM ----------------
// K-chunk 64 fp16 = 128 B rows (+16 B pad = 144 B). 3-stage, wait_group 1, 1 barrier/chunk.
// 8 warps 2(M) x 4(N); warp tile 64x32. 4 k16 steps/chunk. fp32 accumulate.
// MODE 0: h = gelu(xbuf @ W1^T + b1) -> g_h (fp16)
// MODE 1: atomicAdd gate * (h @ W2^T + b2 + x[tok]) into y
#define ROWPAD 36
#define STAGE_F ((128 + 128) * ROWPAD)
#define STAGEB (STAGE_F * 4)                // 36864 B per stage
#define NSTAGE 3
#define SMEM_FFN (NSTAGE * STAGEB)          // 110592 B -> 2 CTAs/SM
#define BOFF (128 * ROWPAD * 4)

template<int KTOT, int MODE>
__global__ void __launch_bounds__(256, 2)
k_ffn(const float* __restrict__ x, const __half* __restrict__ W,
      const float* __restrict__ bias, float* __restrict__ y) {
    extern __shared__ float smf[];
    const uint32_t sb = smem_u32(smf);
    int e = blockIdx.z;
    int nrows = g_rows_used[e];
    int row0 = blockIdx.y * 128;
    if (row0 >= nrows) return;
    int col0 = blockIdx.x * 128;
    int tid = threadIdx.x, wid = tid >> 5, lane = tid & 31;
    int wm = wid & 1, wn = wid >> 1;            // 2(M) x 4(N)
    int gid = lane >> 2, tig = lane & 3;

    const __half* Abase = (MODE ? g_h : g_xbuf) + ((size_t)e * CAP + row0) * KTOT;
    const __half* Bbase = W + (size_t)e * (size_t)(MODE ? DIM : FDIM) * KTOT
                            + (size_t)col0 * KTOT;

    int urow = tid >> 1, uhalf = tid & 1;
    const __half* gA = Abase + (size_t)urow * KTOT + uhalf * 32;
    const __half* gB = Bbase + (size_t)urow * KTOT + uhalf * 32;
    uint32_t sAoff = urow * (ROWPAD * 4) + uhalf * 64;
    uint32_t sBoff = BOFF + sAoff;

    uint32_t aAddr = (wm * 64 + (lane & 15)) * (ROWPAD * 4) + (lane >> 4) * 16;
    uint32_t bAddr = BOFF + (wn * 32 + ((lane >> 4) & 1) * 8 + (lane & 7)) * (ROWPAD * 4)
                     + ((lane >> 3) & 1) * 16;

    float acc[4][4][4];
#pragma unroll
    for (int i = 0; i < 4; i++)
#pragma unroll
        for (int j = 0; j < 4; j++)
#pragma unroll
            for (int q = 0; q < 4; q++) acc[i][j][q] = 0.f;

    const int NKC = KTOT / 64;

#pragma unroll
    for (int pi = 0; pi < 2; pi++) {
        uint32_t st = sb + pi * STAGEB;
        int ko = pi * 64;
#pragma unroll
        for (int g = 0; g < 4; g++) {
            cpa16(st + sAoff + g * 16, gA + ko + g * 8);
            cpa16(st + sBoff + g * 16, gB + ko + g * 8);
        }
        CP_COMMIT();
    }

    int sidx = 0;
    for (int i = 0; i < NKC; i++) {
        asm volatile("cp.async.wait_group 1;");
        __syncthreads();

        if (i + 2 < NKC) {
            int ko = (i + 2) * 64;
            int s2 = sidx + 2; if (s2 >= NSTAGE) s2 -= NSTAGE;
            uint32_t st = sb + s2 * STAGEB;
#pragma unroll
            for (int g = 0; g < 4; g++) {
                cpa16(st + sAoff + g * 16, gA + ko + g * 8);
                cpa16(st + sBoff + g * 16, gB + ko + g * 8);
            }
        }
        CP_COMMIT();

        uint32_t base = sb + sidx * STAGEB;
#pragma unroll
        for (int kk = 0; kk < 4; kk++) {
            uint32_t aF[4][4], bF[4][2];
#pragma unroll
            for (int mt = 0; mt < 4; mt++)
                ldsm4(base + aAddr + mt * 16 * (ROWPAD * 4) + kk * 32,
                      aF[mt][0], aF[mt][1], aF[mt][2], aF[mt][3]);
#pragma unroll
            for (int p = 0; p < 2; p++) {
                uint32_t r0, r1, r2, r3;
                ldsm4(base + bAddr + p * 16 * (ROWPAD * 4) + kk * 32, r0, r1, r2, r3);
                bF[2 * p][0] = r0; bF[2 * p][1] = r1;
                bF[2 * p + 1][0] = r2; bF[2 * p + 1][1] = r3;
            }
#pragma unroll
            for (int mt = 0; mt < 4; mt++)
#pragma unroll
                for (int nt = 0; nt < 4; nt++)
                    mma_f16(acc[mt][nt][0], acc[mt][nt][1], acc[mt][nt][2], acc[mt][nt][3],
                            aF[mt][0], aF[mt][1], aF[mt][2], aF[mt][3],
                            bF[nt][0], bF[nt][1]);
        }
        sidx++; if (sidx >= NSTAGE) sidx -= NSTAGE;
    }

    // ---------------- epilogue ----------------
    const float* bb = bias + (size_t)e * (MODE ? DIM : FDIM) + col0;
#pragma unroll
    for (int mt = 0; mt < 4; mt++) {
        int r0g = row0 + wm * 64 + mt * 16 + gid;
#pragma unroll
        for (int hf = 0; hf < 2; hf++) {
            int rg = r0g + hf * 8;
            if (rg >= nrows) continue;
            const float* xr = nullptr;
            float* yr = nullptr;
            float gw = 0.f;
            if (MODE == 1) {
                int tk = g_rowsrc[e * CAP + rg];
                xr = x + (size_t)tk * DIM + col0;
                yr = y + (size_t)tk * DIM + col0;
                gw = g_gatew[e * CAP + rg];
            }
#pragma unroll
            for (int nt = 0; nt < 4; nt++) {
                int c = wn * 32 + nt * 8 + tig * 2;
                float v0 = acc[mt][nt][hf * 2 + 0] + bb[c];
                float v1 = acc[mt][nt][hf * 2 + 1] + bb[c + 1];
                if (MODE == 0) {
                    v0 = 0.5f * v0 * (1.f + erff(v0 * 0.70710678118654752f));
                    v1 = 0.5f * v1 * (1.f + erff(v1 * 0.70710678118654752f));
                    size_t idx = ((size_t)e * CAP + rg) * FDIM + col0 + c;
                    __half2 hp;
                    hp.x = __float2half_rn(v0); hp.y = __float2half_rn(v1);
                    *(__half2*)(g_h + idx) = hp;
                } else {
                    v0 = gw * (v0 + xr[c]);
                    v1 = gw * (v1 + xr[c + 1]);
                    atomicAdd(yr + c, v0);
                    atomicAdd(yr + c + 1, v1);
                }
            }
        }
    }
}

// ---------------- launch (ffn1 is launch #4 — the one ncu captures) ----------------
extern "C" void kernel_launch(void* const* d_in, const int* in_sizes, int n_in,
                              void* d_out, int out_size) {
    const float* x  = (const float*)d_in[0];
    const float* wg = (const float*)d_in[1];
    const float* W1 = (const float*)d_in[2];
    const float* b1 = (const float*)d_in[3];
    const float* W2 = (const float*)d_in[4];
    const float* b2 = (const float*)d_in[5];
    float* out = (float*)d_out;

    __half *w1h, *w2h;
    cudaGetSymbolAddress((void**)&w1h, g_w1h);
    cudaGetSymbolAddress((void**)&w2h, g_w2h);

    cudaFuncSetAttribute(k_ffn<1024, 0>, cudaFuncAttributeMaxDynamicSharedMemorySize, SMEM_FFN);
    cudaFuncSetAttribute(k_ffn<4096, 1>, cudaFuncAttributeMaxDynamicSharedMemorySize, SMEM_FFN);

    k_route_conv<<<NBLK_ROUTE + NCONV, 256>>>(x, wg, W1, W2, out);  // 1
    k_scan<<<1, 256>>>(out, out_size);                              // 2

    dim3 gd(CAP, NE);
    k_dispatch<<<gd, 256>>>(x);                                     // 3

    dim3 g1(FDIM / 128, CAP / 128, NE);                             // (32, 20, 8)
    k_ffn<1024, 0><<<g1, 256, SMEM_FFN>>>(x, w1h, b1, out);         // 4 <-- profiled

    dim3 g2(DIM / 128, CAP / 128, NE);                              // (8, 20, 8)
    k_ffn<4096, 1><<<g2, 256, SMEM_FFN>>>(x, w2h, b2, out);         // 5
}

// round 16
// speedup vs baseline: 1.5366x; 1.5366x over previous
#include <cuda_runtime.h>
#include <cuda_fp16.h>
#include <math.h>
#include <stdint.h>

#define S_TOK 8192
#define DIM   1024
#define FDIM  4096
#define NE    8
#define CAP   2560
#define NA    (S_TOK * 2)
#define NBLK_ROUTE (S_TOK / 8)

// ---------------- static scratch ----------------
__device__ __align__(256) float g_impb[NBLK_ROUTE * NE];
__device__ __align__(256) int   g_topk_e[NA];
__device__ __align__(256) float g_topk_g[NA];
__device__ __align__(256) int   g_pos[NA];
__device__ __align__(256) int   g_rowsrc[NE * CAP];
__device__ __align__(256) int   g_rows_used[NE];
__device__ __align__(256) __half g_xbuf[(size_t)NE * CAP * DIM];
__device__ __align__(256) __half g_h[(size_t)NE * CAP * FDIM];
__device__ __align__(256) float  g_eout[(size_t)NE * CAP * DIM];
__device__ __align__(256) __half g_w1h[(size_t)NE * FDIM * DIM];
__device__ __align__(256) __half g_w2h[(size_t)NE * DIM * FDIM];

// ---------------- helpers ----------------
__device__ __forceinline__ uint32_t smem_u32(const void* p) {
    uint32_t r;
    asm("{ .reg .u64 t; cvta.to.shared.u64 t, %1; cvt.u32.u64 %0, t; }" : "=r"(r) : "l"(p));
    return r;
}
__device__ __forceinline__ void cpa16(uint32_t s, const void* g) {
    asm volatile("cp.async.cg.shared.global [%0], [%1], 16;" :: "r"(s), "l"(g));
}
#define CP_COMMIT() asm volatile("cp.async.commit_group;")

__device__ __forceinline__ void ldsm4(uint32_t addr, uint32_t& r0, uint32_t& r1,
                                      uint32_t& r2, uint32_t& r3) {
    asm volatile("ldmatrix.sync.aligned.m8n8.x4.shared.b16 {%0,%1,%2,%3}, [%4];"
                 : "=r"(r0), "=r"(r1), "=r"(r2), "=r"(r3) : "r"(addr));
}
__device__ __forceinline__ void mma_f16(float& c0, float& c1, float& c2, float& c3,
                                        uint32_t a0, uint32_t a1, uint32_t a2, uint32_t a3,
                                        uint32_t b0, uint32_t b1) {
    asm volatile("mma.sync.aligned.m16n8k16.row.col.f32.f16.f16.f32 "
                 "{%0,%1,%2,%3}, {%4,%5,%6,%7}, {%8,%9}, {%0,%1,%2,%3};"
                 : "+f"(c0), "+f"(c1), "+f"(c2), "+f"(c3)
                 : "r"(a0), "r"(a1), "r"(a2), "r"(a3), "r"(b0), "r"(b1));
}

// ---------------- route + weight fp16 conversion, one kernel ----------------
#define NCONV 4096
#define W1F4 ((size_t)NE * FDIM * DIM / 4)     // 8388608 float4 per weight

__global__ void k_route_conv(const float* __restrict__ x, const float* __restrict__ wg,
                             const float* __restrict__ W1, const float* __restrict__ W2) {
    int bid = blockIdx.x;
    int tid = threadIdx.x;

    if (bid >= NBLK_ROUTE) {
        // ---- weight fp16 conversion: 4096 blocks x 16 float4/thread ----
        size_t base4 = (size_t)(bid - NBLK_ROUTE) * 4096 + tid;
#pragma unroll
        for (int k = 0; k < 16; k++) {
            size_t i4 = base4 + (size_t)k * 256;
            const float4* src;
            __half* dst;
            size_t off;
            if (i4 < W1F4) { src = (const float4*)W1; dst = g_w1h; off = i4; }
            else           { src = (const float4*)W2; dst = g_w2h; off = i4 - W1F4; }
            float4 v = src[off];
            __half h[4] = { __float2half_rn(v.x), __float2half_rn(v.y),
                            __float2half_rn(v.z), __float2half_rn(v.w) };
            *(uint2*)(dst + off * 4) = *(uint2*)h;
        }
        return;
    }

    // ---- routing: warp per token ----
    __shared__ float sw[NE * DIM];
    __shared__ float simp[NE];

    const float4* wg4 = (const float4*)wg;
    float4* sw4 = (float4*)sw;
    for (int i = tid; i < NE * DIM / 4; i += 256) sw4[i] = wg4[i];
    if (tid < NE) simp[tid] = 0.f;
    __syncthreads();

    int warp = tid >> 5, lane = tid & 31;
    int t = bid * 8 + warp;

    const float4* x4 = (const float4*)(x + (size_t)t * DIM);
    float acc[NE];
#pragma unroll
    for (int e = 0; e < NE; e++) acc[e] = 0.f;
#pragma unroll
    for (int i = 0; i < 8; i++) {
        float4 xv = x4[lane + i * 32];
#pragma unroll
        for (int e = 0; e < NE; e++) {
            float4 wv = ((const float4*)(sw + e * DIM))[lane + i * 32];
            acc[e] += xv.x * wv.x + xv.y * wv.y + xv.z * wv.z + xv.w * wv.w;
        }
    }
#pragma unroll
    for (int e = 0; e < NE; e++) {
#pragma unroll
        for (int off = 16; off > 0; off >>= 1)
            acc[e] += __shfl_xor_sync(0xffffffffu, acc[e], off);
    }

    if (lane == 0) {
        float m = acc[0];
#pragma unroll
        for (int e = 1; e < NE; e++) m = fmaxf(m, acc[e]);
        float p[NE];
        float s = 0.f;
#pragma unroll
        for (int e = 0; e < NE; e++) { p[e] = expf(acc[e] - m); s += p[e]; }
        float inv = 1.f / s;
#pragma unroll
        for (int e = 0; e < NE; e++) { p[e] *= inv; atomicAdd(&simp[e], p[e]); }

        int e0 = 0;
#pragma unroll
        for (int e = 1; e < NE; e++) if (p[e] > p[e0]) e0 = e;
        int e1 = (e0 == 0) ? 1 : 0;
#pragma unroll
        for (int e = 0; e < NE; e++) if (e != e0 && p[e] > p[e1]) e1 = e;

        g_topk_e[2 * t]     = e0;  g_topk_g[2 * t]     = p[e0];
        g_topk_e[2 * t + 1] = e1;  g_topk_g[2 * t + 1] = p[e1];
    }
    __syncthreads();
    if (tid < NE) g_impb[bid * NE + tid] = simp[tid];
}

// ---------------- exact arrival-order capacity scan + aux loss ----------------
__global__ void k_scan(float* __restrict__ out, int out_size) {
    __shared__ int scnt[256][NE];
    __shared__ int stot[NE];
    __shared__ float simp[NE];
    int tid = threadIdx.x;

    if (tid < NE) simp[tid] = 0.f;
    __syncthreads();
    {
        float part = 0.f;
        int e = tid & 7;
        for (int i = tid >> 3; i < NBLK_ROUTE; i += 32) part += g_impb[i * NE + e];
        atomicAdd(&simp[e], part);
    }

    int cnt[NE];
#pragma unroll
    for (int e = 0; e < NE; e++) cnt[e] = 0;
    int base = tid * 64;
    for (int j = 0; j < 64; j++) cnt[g_topk_e[base + j]]++;
#pragma unroll
    for (int e = 0; e < NE; e++) scnt[tid][e] = cnt[e];
    __syncthreads();

    if (tid < NE) {
        int run = 0;
        for (int i = 0; i < 256; i++) {
            int v = scnt[i][tid];
            scnt[i][tid] = run;
            run += v;
        }
        stot[tid] = run;
        g_rows_used[tid] = run < CAP ? run : CAP;
    }
    __syncthreads();

#pragma unroll
    for (int e = 0; e < NE; e++) cnt[e] = scnt[tid][e];
    for (int j = 0; j < 64; j++) {
        int a = base + j;
        int e = g_topk_e[a];
        int p = cnt[e]++;
        g_pos[a] = p;
        if (p < CAP) g_rowsrc[e * CAP + p] = a >> 1;
    }

    if (tid == 0) {
        float ssum = 0.f;
        for (int e = 0; e < NE; e++)
            ssum += (simp[e] / (float)S_TOK) * ((float)stot[e] / (float)S_TOK);
        if (out_size > S_TOK * DIM) out[S_TOK * DIM] = (float)NE * ssum;
    }
}

// ---------------- dispatch tokens (fp16) ----------------
__global__ void k_dispatch(const float* __restrict__ x) {
    int p = blockIdx.x, e = blockIdx.y;
    int tid = threadIdx.x;
    size_t base = ((size_t)e * CAP + p) * DIM + tid * 4;
    float4 v;
    if (p < g_rows_used[e]) {
        v = *(const float4*)(x + (size_t)g_rowsrc[e * CAP + p] * DIM + tid * 4);
    } else {
        v = make_float4(0.f, 0.f, 0.f, 0.f);
    }
    __half h[4] = { __float2half_rn(v.x), __float2half_rn(v.y),
                    __float2half_rn(v.z), __float2half_rn(v.w) };
    *(uint2*)(g_xbuf + base) = *(uint2*)h;
}

// ---------------- mma.sync fp16 FFN GEMM: 128x128 tile, 8 warps, 2 CTAs/SM ----------------
// K-chunk 64 fp16 = 128 B rows (+16 B pad = 144 B). 3-stage, wait_group 1, 1 barrier/chunk.
// 8 warps 2(M) x 4(N); warp tile 64x32. 4 k16 steps/chunk. fp32 accumulate.
#define ROWPAD 36
#define STAGE_F ((128 + 128) * ROWPAD)
#define STAGEB (STAGE_F * 4)                // 36864 B per stage
#define NSTAGE 3
#define SMEM_FFN (NSTAGE * STAGEB)          // 110592 B -> 2 CTAs/SM
#define BOFF (128 * ROWPAD * 4)

template<int KTOT, int MODE>
__global__ void __launch_bounds__(256, 2)
k_ffn(const float* __restrict__ x, const __half* __restrict__ W,
      const float* __restrict__ bias) {
    extern __shared__ float smf[];
    const uint32_t sb = smem_u32(smf);
    int e = blockIdx.z;
    int nrows = g_rows_used[e];
    int row0 = blockIdx.y * 128;
    if (row0 >= nrows) return;
    int col0 = blockIdx.x * 128;
    int tid = threadIdx.x, wid = tid >> 5, lane = tid & 31;
    int wm = wid & 1, wn = wid >> 1;            // 2(M) x 4(N)
    int gid = lane >> 2, tig = lane & 3;

    const __half* Abase = (MODE ? g_h : g_xbuf) + ((size_t)e * CAP + row0) * KTOT;
    const __half* Bbase = W + (size_t)e * (size_t)(MODE ? DIM : FDIM) * KTOT
                            + (size_t)col0 * KTOT;

    int urow = tid >> 1, uhalf = tid & 1;
    const __half* gA = Abase + (size_t)urow * KTOT + uhalf * 32;
    const __half* gB = Bbase + (size_t)urow * KTOT + uhalf * 32;
    uint32_t sAoff = urow * (ROWPAD * 4) + uhalf * 64;
    uint32_t sBoff = BOFF + sAoff;

    uint32_t aAddr = (wm * 64 + (lane & 15)) * (ROWPAD * 4) + (lane >> 4) * 16;
    uint32_t bAddr = BOFF + (wn * 32 + ((lane >> 4) & 1) * 8 + (lane & 7)) * (ROWPAD * 4)
                     + ((lane >> 3) & 1) * 16;

    float acc[4][4][4];
#pragma unroll
    for (int i = 0; i < 4; i++)
#pragma unroll
        for (int j = 0; j < 4; j++)
#pragma unroll
            for (int q = 0; q < 4; q++) acc[i][j][q] = 0.f;

    const int NKC = KTOT / 64;

#pragma unroll
    for (int pi = 0; pi < 2; pi++) {
        uint32_t st = sb + pi * STAGEB;
        int ko = pi * 64;
#pragma unroll
        for (int g = 0; g < 4; g++) {
            cpa16(st + sAoff + g * 16, gA + ko + g * 8);
            cpa16(st + sBoff + g * 16, gB + ko + g * 8);
        }
        CP_COMMIT();
    }

    int sidx = 0;
    for (int i = 0; i < NKC; i++) {
        asm volatile("cp.async.wait_group 1;");
        __syncthreads();

        if (i + 2 < NKC) {
            int ko = (i + 2) * 64;
            int s2 = sidx + 2; if (s2 >= NSTAGE) s2 -= NSTAGE;
            uint32_t st = sb + s2 * STAGEB;
#pragma unroll
            for (int g = 0; g < 4; g++) {
                cpa16(st + sAoff + g * 16, gA + ko + g * 8);
                cpa16(st + sBoff + g * 16, gB + ko + g * 8);
            }
        }
        CP_COMMIT();

        uint32_t base = sb + sidx * STAGEB;
#pragma unroll
        for (int kk = 0; kk < 4; kk++) {
            uint32_t aF[4][4], bF[4][2];
#pragma unroll
            for (int mt = 0; mt < 4; mt++)
                ldsm4(base + aAddr + mt * 16 * (ROWPAD * 4) + kk * 32,
                      aF[mt][0], aF[mt][1], aF[mt][2], aF[mt][3]);
#pragma unroll
            for (int p = 0; p < 2; p++) {
                uint32_t r0, r1, r2, r3;
                ldsm4(base + bAddr + p * 16 * (ROWPAD * 4) + kk * 32, r0, r1, r2, r3);
                bF[2 * p][0] = r0; bF[2 * p][1] = r1;
                bF[2 * p + 1][0] = r2; bF[2 * p + 1][1] = r3;
            }
#pragma unroll
            for (int mt = 0; mt < 4; mt++)
#pragma unroll
                for (int nt = 0; nt < 4; nt++)
                    mma_f16(acc[mt][nt][0], acc[mt][nt][1], acc[mt][nt][2], acc[mt][nt][3],
                            aF[mt][0], aF[mt][1], aF[mt][2], aF[mt][3],
                            bF[nt][0], bF[nt][1]);
        }
        sidx++; if (sidx >= NSTAGE) sidx -= NSTAGE;
    }

    // ---------------- epilogue ----------------
    const float* bb = bias + (size_t)e * (MODE ? DIM : FDIM) + col0;
#pragma unroll
    for (int mt = 0; mt < 4; mt++) {
        int r0g = row0 + wm * 64 + mt * 16 + gid;
#pragma unroll
        for (int hf = 0; hf < 2; hf++) {
            int rg = r0g + hf * 8;
            if (rg >= nrows) continue;
            const float* xr = nullptr;
            if (MODE == 1) {
                int tk = g_rowsrc[e * CAP + rg];
                xr = x + (size_t)tk * DIM + col0;
            }
#pragma unroll
            for (int nt = 0; nt < 4; nt++) {
                int c = wn * 32 + nt * 8 + tig * 2;
                float v0 = acc[mt][nt][hf * 2 + 0] + bb[c];
                float v1 = acc[mt][nt][hf * 2 + 1] + bb[c + 1];
                if (MODE == 0) {
                    v0 = 0.5f * v0 * (1.f + erff(v0 * 0.70710678118654752f));
                    v1 = 0.5f * v1 * (1.f + erff(v1 * 0.70710678118654752f));
                    size_t idx = ((size_t)e * CAP + rg) * FDIM + col0 + c;
                    __half2 hp;
                    hp.x = __float2half_rn(v0); hp.y = __float2half_rn(v1);
                    *(__half2*)(g_h + idx) = hp;
                } else {
                    v0 += xr[c]; v1 += xr[c + 1];
                    size_t idx = ((size_t)e * CAP + rg) * DIM + col0 + c;
                    *(float2*)(g_eout + idx) = make_float2(v0, v1);
                }
            }
        }
    }
}

// ---------------- combine ----------------
__global__ void k_combine(float* __restrict__ y) {
    int t = blockIdx.x;
    int tid = threadIdx.x;
    int a0 = 2 * t, a1 = a0 + 1;

    int e0 = g_topk_e[a0], p0 = g_pos[a0]; float gv0 = g_topk_g[a0];
    int e1 = g_topk_e[a1], p1 = g_pos[a1]; float gv1 = g_topk_g[a1];

    float4 r;
    r.x = 0.f; r.y = 0.f; r.z = 0.f; r.w = 0.f;

    if (p0 < CAP) {
        const float4* s = (const float4*)(g_eout + ((size_t)e0 * CAP + p0) * DIM);
        float4 v = s[tid];
        r.x += gv0 * v.x; r.y += gv0 * v.y; r.z += gv0 * v.z; r.w += gv0 * v.w;
    }
    if (p1 < CAP) {
        const float4* s = (const float4*)(g_eout + ((size_t)e1 * CAP + p1) * DIM);
        float4 v = s[tid];
        r.x += gv1 * v.x; r.y += gv1 * v.y; r.z += gv1 * v.z; r.w += gv1 * v.w;
    }
    ((float4*)(y + (size_t)t * DIM))[tid] = r;
}

// ---------------- launch (ffn1 is launch #4 — the one ncu captures) ----------------
extern "C" void kernel_launch(void* const* d_in, const int* in_sizes, int n_in,
                              void* d_out, int out_size) {
    const float* x  = (const float*)d_in[0];
    const float* wg = (const float*)d_in[1];
    const float* W1 = (const float*)d_in[2];
    const float* b1 = (const float*)d_in[3];
    const float* W2 = (const float*)d_in[4];
    const float* b2 = (const float*)d_in[5];
    float* out = (float*)d_out;

    __half *w1h, *w2h;
    cudaGetSymbolAddress((void**)&w1h, g_w1h);
    cudaGetSymbolAddress((void**)&w2h, g_w2h);

    cudaFuncSetAttribute(k_ffn<1024, 0>, cudaFuncAttributeMaxDynamicSharedMemorySize, SMEM_FFN);
    cudaFuncSetAttribute(k_ffn<4096, 1>, cudaFuncAttributeMaxDynamicSharedMemorySize, SMEM_FFN);

    k_route_conv<<<NBLK_ROUTE + NCONV, 256>>>(x, wg, W1, W2);   // 1
    k_scan<<<1, 256>>>(out, out_size);                          // 2

    dim3 gd(CAP, NE);
    k_dispatch<<<gd, 256>>>(x);                                 // 3

    dim3 g1(FDIM / 128, CAP / 128, NE);                         // (32, 20, 8)
    k_ffn<1024, 0><<<g1, 256, SMEM_FFN>>>(x, w1h, b1);          // 4 <-- profiled

    dim3 g2(DIM / 128, CAP / 128, NE);                          // (8, 20, 8)
    k_ffn<4096, 1><<<g2, 256, SMEM_FFN>>>(x, w2h, b2);          // 5

    k_combine<<<S_TOK, 256>>>(out);                             // 6
}